// round 5
// baseline (speedup 1.0000x reference)
#include <cuda_runtime.h>
#include <cstdint>
#include <cstddef>

#define S_LEN 2048
#define BATCH 32
#define EMB   512
#define HID   256
#define G3    768
#define M_ROWS (S_LEN * BATCH)              // 65536
#define OUT0  ((size_t)S_LEN * BATCH * 512) // offset of hidden in d_out

typedef unsigned long long u64;
typedef uint32_t u32;

// ---------------- scratch (static device allocation; no cudaMalloc) --------
__device__ float gi_buf[(size_t)2 * M_ROWS * G3];   // ~402 MB: gi for both dirs

// ---------------- packed f32x2 helpers ------------------------------------
__device__ __forceinline__ u64 fma2(u64 a, u64 b, u64 c) {
    u64 d;
    asm("fma.rn.f32x2 %0, %1, %2, %3;" : "=l"(d) : "l"(a), "l"(b), "l"(c));
    return d;
}
__device__ __forceinline__ u64 pack2(float x, float y) {
    u64 r;
    asm("mov.b64 %0, {%1, %2};" : "=l"(r) : "f"(x), "f"(y));
    return r;
}
__device__ __forceinline__ float2 unpack2(u64 v) {
    float2 f;
    asm("mov.b64 {%0, %1}, %2;" : "=f"(f.x), "=f"(f.y) : "l"(v));
    return f;
}
__device__ __forceinline__ u32 smem_u32(const void* p) {
    u32 a;
    asm("{ .reg .u64 t; cvta.to.shared.u64 t, %1; cvt.u32.u64 %0, t; }"
        : "=r"(a) : "l"(p));
    return a;
}

// ---------------- gi GEMM (unchanged; passed at ~2.4 ms) -------------------
#define BM 128
#define BN 128
#define BK 16

__global__ __launch_bounds__(256, 2) void gi_gemm(
    const float* __restrict__ x,
    const float* __restrict__ wf, const float* __restrict__ bf,
    const float* __restrict__ wb, const float* __restrict__ bb)
{
    __shared__ float As[BK][BM];
    __shared__ float Ws[BK][BN];

    const int d  = blockIdx.z;
    const float* __restrict__ w  = d ? wb : wf;
    const float* __restrict__ bi = d ? bb : bf;
    const int m0 = blockIdx.y * BM;
    const int g0 = blockIdx.x * BN;
    const int tid = threadIdx.x;

    const int lr = tid >> 1;
    const int lk = (tid & 1) * 8;
    const int tx = tid & 15;
    const int ty = tid >> 4;

    u64 acc[4][8];
#pragma unroll
    for (int i = 0; i < 4; i++)
#pragma unroll
        for (int j = 0; j < 8; j++) acc[i][j] = 0ull;

    const float* xp = &x[(size_t)(m0 + lr) * EMB + lk];
    const float* wp = &w[(size_t)(g0 + lr) * EMB + lk];

    float4 a0r = *(const float4*)(xp);
    float4 a1r = *(const float4*)(xp + 4);
    float4 w0r = *(const float4*)(wp);
    float4 w1r = *(const float4*)(wp + 4);

    for (int kt = 0; kt < EMB; kt += BK) {
        As[lk + 0][lr] = a0r.x; As[lk + 1][lr] = a0r.y;
        As[lk + 2][lr] = a0r.z; As[lk + 3][lr] = a0r.w;
        As[lk + 4][lr] = a1r.x; As[lk + 5][lr] = a1r.y;
        As[lk + 6][lr] = a1r.z; As[lk + 7][lr] = a1r.w;
        Ws[lk + 0][lr] = w0r.x; Ws[lk + 1][lr] = w0r.y;
        Ws[lk + 2][lr] = w0r.z; Ws[lk + 3][lr] = w0r.w;
        Ws[lk + 4][lr] = w1r.x; Ws[lk + 5][lr] = w1r.y;
        Ws[lk + 6][lr] = w1r.z; Ws[lk + 7][lr] = w1r.w;
        __syncthreads();

        if (kt + BK < EMB) {
            a0r = *(const float4*)(xp + kt + BK);
            a1r = *(const float4*)(xp + kt + BK + 4);
            w0r = *(const float4*)(wp + kt + BK);
            w1r = *(const float4*)(wp + kt + BK + 4);
        }

#pragma unroll
        for (int k = 0; k < BK; k++) {
            u64 am[4];
#pragma unroll
            for (int i = 0; i < 4; i++)
                am[i] = *(const u64*)&As[k][ty * 8 + i * 2];
            float4 v0 = *(const float4*)&Ws[k][tx * 8];
            float4 v1 = *(const float4*)&Ws[k][tx * 8 + 4];
            u64 wd[8];
            wd[0] = pack2(v0.x, v0.x); wd[1] = pack2(v0.y, v0.y);
            wd[2] = pack2(v0.z, v0.z); wd[3] = pack2(v0.w, v0.w);
            wd[4] = pack2(v1.x, v1.x); wd[5] = pack2(v1.y, v1.y);
            wd[6] = pack2(v1.z, v1.z); wd[7] = pack2(v1.w, v1.w);
#pragma unroll
            for (int i = 0; i < 4; i++)
#pragma unroll
                for (int j = 0; j < 8; j++)
                    acc[i][j] = fma2(am[i], wd[j], acc[i][j]);
        }
        __syncthreads();
    }

    const int gcol = g0 + tx * 8;
    const size_t base = (size_t)d * M_ROWS * G3;
    float bv[8];
#pragma unroll
    for (int j = 0; j < 8; j++) bv[j] = bi[gcol + j];

#pragma unroll
    for (int i = 0; i < 4; i++) {
        const int m = m0 + ty * 8 + i * 2;
        float o0[8], o1[8];
#pragma unroll
        for (int j = 0; j < 8; j++) {
            float2 f = unpack2(acc[i][j]);
            o0[j] = f.x + bv[j];
            o1[j] = f.y + bv[j];
        }
        *(float4*)&gi_buf[base + (size_t)(m + 0) * G3 + gcol]     = *(float4*)&o0[0];
        *(float4*)&gi_buf[base + (size_t)(m + 0) * G3 + gcol + 4] = *(float4*)&o0[4];
        *(float4*)&gi_buf[base + (size_t)(m + 1) * G3 + gcol]     = *(float4*)&o1[0];
        *(float4*)&gi_buf[base + (size_t)(m + 1) * G3 + gcol + 4] = *(float4*)&o1[4];
    }
}

// ---------------- GRU scan: plain DSMEM stores + count-based mbarriers -----
// 128 blocks = 16 clusters of 8. Cluster = (dir, batch-group of 4 batches);
// rank = j-chunk (32 h-dims). Per step, each CTA:
//   wait(mbar[rb], 8 arrives)  -> matvec on h[rb] -> syncthreads ->
//   gates + plain st.shared::cluster pushes of h(s+1) into all 8 CTAs'
//   h[nb] -> syncthreads -> t0: one release-arrive on each CTA's mbar[nb].
// Release is cumulative over the __syncthreads edge, so the arrive carries
// all of this CTA's pushes. No st.async, no expect_tx, no in-loop
// barrier.cluster. Phase mixing impossible: any arrive into a consumer's
// next phase transitively requires that consumer's own current-phase arrive.

struct ScanSmem {
    float h[2][4 * HID];        // double-buffered h (4 KB each)
    float4 psum[4 * 96];        // k-slice partial sums
    u64 mbar[2];                // one mbarrier per h buffer (count = 8)
};

__global__ __launch_bounds__(384, 1) __cluster_dims__(8, 1, 1)
void gru_scan(
    const float* __restrict__ whh_f, const float* __restrict__ bhh_f,
    const float* __restrict__ whh_b, const float* __restrict__ bhh_b,
    float* __restrict__ out)
{
    __shared__ __align__(16) ScanSmem sm;

    const int bx  = blockIdx.x;
    const int jc  = bx & 7;         // cluster rank = j-chunk
    const int grp = bx >> 3;
    const int bg  = grp & 7;        // batch group 0..7
    const int d   = grp >> 3;       // direction
    const int j0  = jc * 32;

    const float* __restrict__ whh = d ? whh_b : whh_f;
    const float* __restrict__ bhh = d ? bhh_b : bhh_f;

    const int t    = threadIdx.x;
    const int ks   = t / 96;        // k-slice 0..3 (warp-uniform)
    const int rl   = t % 96;        // gate*32 + jj
    const int gate = rl >> 5;
    const int jj   = rl & 31;
    const int rowg = gate * 256 + j0 + jj;

    // pin weight slice in registers (64 floats = 32 packed pairs)
    u64 w2[32];
    {
        const u64* wpt = (const u64*)(whh + (size_t)rowg * HID + ks * 64);
#pragma unroll
        for (int i = 0; i < 32; i++) w2[i] = wpt[i];
    }

    const u32 loc_h  = smem_u32(&sm.h[0][0]);
    const u32 loc_mb = smem_u32(&sm.mbar[0]);

    // remote addresses for all 8 cluster CTAs (h base + mbar base)
    u32 rh[8], rmb[8];
#pragma unroll
    for (int r = 0; r < 8; r++) {
        asm("mapa.shared::cluster.u32 %0, %1, %2;"
            : "=r"(rh[r]) : "r"(loc_h), "r"(r));
        asm("mapa.shared::cluster.u32 %0, %1, %2;"
            : "=r"(rmb[r]) : "r"(loc_mb), "r"(r));
    }

    // gate-thread identity (t < 128)
    const int gjj   = t >> 2;
    const int gb    = t & 3;
    const int bglob = bg * 4 + gb;
    float bh0 = 0.f, bh1 = 0.f, bh2 = 0.f;
    if (t < 128) {
        bh0 = bhh[j0 + gjj];
        bh1 = bhh[256 + j0 + gjj];
        bh2 = bhh[512 + j0 + gjj];
    }

    // init: zero h buffer 0, init mbarriers (count = 8 producer CTAs)
    for (int idx = t; idx < 4 * HID; idx += 384) sm.h[0][idx] = 0.f;
    if (t == 0) {
        asm volatile("mbarrier.init.shared.b64 [%0], 8;" :: "r"(loc_mb) : "memory");
        asm volatile("mbarrier.init.shared.b64 [%0], 8;" :: "r"(loc_mb + 8) : "memory");
        asm volatile("fence.mbarrier_init.release.cluster;" ::: "memory");
    }
    __syncthreads();
    asm volatile("barrier.cluster.arrive.aligned;" ::: "memory");
    asm volatile("barrier.cluster.wait.aligned;"   ::: "memory");

    int par0 = 0, par1 = 0;        // wait parity per mbarrier

    // prefetch gi for step 0
    float gic0 = 0.f, gic1 = 0.f, gic2 = 0.f;
    if (t < 128) {
        const int sidx0 = d ? (S_LEN - 1) : 0;
        const float* gp = gi_buf +
            ((size_t)d * M_ROWS + (size_t)sidx0 * BATCH + bglob) * G3;
        gic0 = gp[j0 + gjj];
        gic1 = gp[256 + j0 + gjj];
        gic2 = gp[512 + j0 + gjj];
    }

    for (int step = 0; step < S_LEN; step++) {
        const int rb = step & 1;
        const int nb = rb ^ 1;
        const int sidx = d ? (S_LEN - 1 - step) : step;

        // wait for own h(step) buffer: 8 arrives (skip step 0: local zeros)
        if (step > 0) {
            const u32 mb = loc_mb + rb * 8;
            const int par = rb ? par1 : par0;
            u32 done;
            asm volatile(
                "{\n\t.reg .pred p;\n\t"
                "mbarrier.try_wait.parity.acquire.cluster.shared::cta.b64 p, [%1], %2;\n\t"
                "selp.b32 %0, 1, 0, p;\n\t}"
                : "=r"(done) : "r"(mb), "r"((u32)par) : "memory");
            if (!done) {
                asm volatile(
                    "{\n\t.reg .pred P1;\n\t"
                    "WL_%=:\n\t"
                    "mbarrier.try_wait.parity.acquire.cluster.shared::cta.b64 P1, [%0], %1, 0x989680;\n\t"
                    "@P1 bra.uni WD_%=;\n\t"
                    "bra.uni WL_%=;\n\t"
                    "WD_%=:\n\t}"
                    :: "r"(mb), "r"((u32)par) : "memory");
            }
            if (rb) par1 ^= 1; else par0 ^= 1;
        }

        // prefetch gi for next step (consumed one step later)
        float gin0 = 0.f, gin1 = 0.f, gin2 = 0.f;
        if (t < 128 && step + 1 < S_LEN) {
            const int sidxn = d ? (S_LEN - 2 - step) : (step + 1);
            const float* gp = gi_buf +
                ((size_t)d * M_ROWS + (size_t)sidxn * BATCH + bglob) * G3;
            gin0 = gp[j0 + gjj];
            gin1 = gp[256 + j0 + gjj];
            gin2 = gp[512 + j0 + gjj];
        }

        // matvec: 4 batches, LDS.128 h reads (warp-uniform broadcast)
        {
            u64 a0 = 0ull, a1 = 0ull, a2 = 0ull, a3 = 0ull;
            const ulonglong2* h0 = (const ulonglong2*)(sm.h[rb] + 0 * HID + ks * 64);
            const ulonglong2* h1 = (const ulonglong2*)(sm.h[rb] + 1 * HID + ks * 64);
            const ulonglong2* h2 = (const ulonglong2*)(sm.h[rb] + 2 * HID + ks * 64);
            const ulonglong2* h3 = (const ulonglong2*)(sm.h[rb] + 3 * HID + ks * 64);
#pragma unroll
            for (int i = 0; i < 16; i++) {
                ulonglong2 v0 = h0[i], v1 = h1[i], v2 = h2[i], v3 = h3[i];
                a0 = fma2(w2[2 * i], v0.x, a0);
                a0 = fma2(w2[2 * i + 1], v0.y, a0);
                a1 = fma2(w2[2 * i], v1.x, a1);
                a1 = fma2(w2[2 * i + 1], v1.y, a1);
                a2 = fma2(w2[2 * i], v2.x, a2);
                a2 = fma2(w2[2 * i + 1], v2.y, a2);
                a3 = fma2(w2[2 * i], v3.x, a3);
                a3 = fma2(w2[2 * i + 1], v3.y, a3);
            }
            float2 f0 = unpack2(a0), f1 = unpack2(a1);
            float2 f2 = unpack2(a2), f3 = unpack2(a3);
            float4 p;
            p.x = f0.x + f0.y; p.y = f1.x + f1.y;
            p.z = f2.x + f2.y; p.w = f3.x + f3.y;
            sm.psum[ks * 96 + rl] = p;
        }
        __syncthreads();

        // gates + h update + plain DSMEM pushes (warps 0-3)
        if (t < 128) {
            const float* pf = (const float*)sm.psum;
            float ghr = bh0, ghz = bh1, ghn = bh2;
#pragma unroll
            for (int k2 = 0; k2 < 4; k2++) {
                ghr += pf[k2 * 384 + t];
                ghz += pf[k2 * 384 + 128 + t];
                ghn += pf[k2 * 384 + 256 + t];
            }
            float hprev = sm.h[rb][gb * HID + j0 + gjj];
            float r = __fdividef(1.f, 1.f + __expf(-(gic0 + ghr)));
            float z = __fdividef(1.f, 1.f + __expf(-(gic1 + ghz)));
            float x2 = gic2 + r * ghn;
            float n = __fdividef(2.f, 1.f + __expf(-2.f * x2)) - 1.f;
            float hy = n + z * (hprev - n);

            // pair adjacent jj via shfl; even-gjj threads push b64 to 8 CTAs
            float hy_up = __shfl_down_sync(0xFFFFFFFFu, hy, 4);
            if ((t & 4) == 0) {
                const u64 val = pack2(hy, hy_up);
                const u32 off = (u32)((nb * 4 * HID + gb * HID + j0 + gjj) * 4);
#pragma unroll
                for (int r8 = 0; r8 < 8; r8++)
                    asm volatile("st.shared::cluster.b64 [%0], %1;"
                                 :: "r"(rh[r8] + off), "l"(val) : "memory");
            }

            out[((size_t)sidx * BATCH + bglob) * 512 + d * HID + j0 + gjj] = hy;
            if (step == S_LEN - 1)
                out[OUT0 + (size_t)(d * BATCH + bglob) * HID + j0 + gjj] = hy;

            gic0 = gin0; gic1 = gin1; gic2 = gin2;
        }
        __syncthreads();   // all pushes happen-before t0's release-arrives

        // t0: one cumulative release-arrive on each cluster CTA's mbar[nb]
        if (t == 0) {
#pragma unroll
            for (int r8 = 0; r8 < 8; r8++)
                asm volatile(
                    "mbarrier.arrive.release.cluster.shared::cluster.b64 _, [%0];"
                    :: "r"(rmb[r8] + (u32)(nb * 8)) : "memory");
        }
    }

    // don't exit while peers' stores into our smem may be in flight
    asm volatile("barrier.cluster.arrive.aligned;" ::: "memory");
    asm volatile("barrier.cluster.wait.aligned;"   ::: "memory");
}

// ---------------- launch ---------------------------------------------------
extern "C" void kernel_launch(void* const* d_in, const int* in_sizes, int n_in,
                              void* d_out, int out_size)
{
    const float* x      = (const float*)d_in[0];
    const float* w_ih_f = (const float*)d_in[1];
    const float* w_hh_f = (const float*)d_in[2];
    const float* b_ih_f = (const float*)d_in[3];
    const float* b_hh_f = (const float*)d_in[4];
    const float* w_ih_b = (const float*)d_in[5];
    const float* w_hh_b = (const float*)d_in[6];
    const float* b_ih_b = (const float*)d_in[7];
    const float* b_hh_b = (const float*)d_in[8];
    float* out = (float*)d_out;

    dim3 gg(G3 / BN, M_ROWS / BM, 2);   // (6, 512, 2)
    gi_gemm<<<gg, 256>>>(x, w_ih_f, b_ih_f, w_ih_b, b_ih_b);

    gru_scan<<<128, 384>>>(w_hh_f, b_hh_f, w_hh_b, b_hh_b, out);
}